// round 1
// baseline (speedup 1.0000x reference)
#include <cuda_runtime.h>
#include <cuda_bf16.h>

#define G   64
#define NN  1000
#define EE  8192
#define C   128
#define HID 256
#define NH  4
#define DH  32
#define LNEPS 1e-5f

#define GNC4 (G*NN*32)   // number of float4 elements in a (G,N,C) buffer

// ---------------- scratch (device globals: no allocations allowed) ----------------
__device__ float4 d_h4[GNC4];     // GEMM output h = X @ W
__device__ float4 d_agg4[GNC4];   // aggregated GCN output
__device__ float4 d_act4[GNC4];   // tanh activation (next layer input)
__device__ float  d_dinv[G*NN];   // 1/sqrt(deg)
__device__ float4 d_gpool4[G*32]; // pooled graph features (G,128)
__device__ float  d_qkv[G*3*C];
__device__ float  d_attn_o[G*C];
__device__ float  d_node[C];      // node_repr accumulator

// ---------------- kernels ----------------

__global__ void k_zero() {
    int i = blockIdx.x * blockDim.x + threadIdx.x;
    if (i < G*32) d_gpool4[i] = make_float4(0.f,0.f,0.f,0.f);
    if (i < C)    d_node[i] = 0.f;
}

// degrees -> dinv.  one block per graph, counts in shared memory.
__global__ void k_deg(const int* __restrict__ ei) {
    int g = blockIdx.x;
    __shared__ float deg[NN];
    for (int i = threadIdx.x; i < NN; i += blockDim.x) deg[i] = 1.0f;
    __syncthreads();
    const int* dst = ei + g*2*EE + EE;
    for (int e = threadIdx.x; e < EE; e += blockDim.x)
        atomicAdd(&deg[dst[e]], 1.0f);
    __syncthreads();
    for (int i = threadIdx.x; i < NN; i += blockDim.x)
        d_dinv[g*NN + i] = rsqrtf(deg[i]);
}

// Y(=d_h4) = X @ W,  X: 64000x128, W: 128x128.  BM=64, full N=128 per block.
// Inner loop uses packed fma.rn.f32x2 (2x fp32 FMA throughput on sm_100a,
// identical IEEE rounding to scalar FFMA).
__global__ void k_gemm(const float* __restrict__ Xext, int useAct,
                       const float* __restrict__ W) {
    const float* X = useAct ? (const float*)d_act4 : Xext;
    float* Y = (float*)d_h4;
    __shared__ __align__(16) float Xs[64][32];
    __shared__ __align__(16) float Ws[32][128];
    int tid = threadIdx.x;              // 256 threads
    int row0 = blockIdx.x * 64;
    int cg = tid & 31;                  // column group: cols cg*4..cg*4+3
    int rg = tid >> 5;                  // row group: rows rg*8..rg*8+7
    unsigned long long acc[8][2];
    #pragma unroll
    for (int i = 0; i < 8; i++) { acc[i][0] = 0ull; acc[i][1] = 0ull; }

    for (int k0 = 0; k0 < 128; k0 += 32) {
        for (int t = tid; t < 512; t += 256) {          // Xs: 64x32
            int r = t >> 3, c4 = t & 7;
            *(float4*)&Xs[r][c4*4] = *(const float4*)&X[(row0 + r)*128 + k0 + c4*4];
        }
        for (int t = tid; t < 1024; t += 256) {         // Ws: 32x128
            int r = t >> 5, c4 = t & 31;
            *(float4*)&Ws[r][c4*4] = *(const float4*)&W[(k0 + r)*128 + c4*4];
        }
        __syncthreads();
        #pragma unroll
        for (int kk = 0; kk < 32; kk++) {
            ulonglong2 w = *(ulonglong2*)&Ws[kk][cg*4];
            #pragma unroll
            for (int i = 0; i < 8; i++) {
                float a = Xs[rg*8 + i][kk];
                unsigned long long ap;
                asm("mov.b64 %0,{%1,%1};" : "=l"(ap) : "f"(a));
                asm("fma.rn.f32x2 %0,%1,%2,%0;" : "+l"(acc[i][0]) : "l"(ap), "l"(w.x));
                asm("fma.rn.f32x2 %0,%1,%2,%0;" : "+l"(acc[i][1]) : "l"(ap), "l"(w.y));
            }
        }
        __syncthreads();
    }
    #pragma unroll
    for (int i = 0; i < 8; i++) {
        float2 lo = *(float2*)&acc[i][0];
        float2 hi = *(float2*)&acc[i][1];
        *(float4*)&Y[(row0 + rg*8 + i)*128 + cg*4] = make_float4(lo.x, lo.y, hi.x, hi.y);
    }
}

// agg = h * dinv^2 + bias   (self-loop term + bias, also zeroes/initializes agg)
__global__ void k_initagg(const float* __restrict__ b) {
    int idx = blockIdx.x * blockDim.x + threadIdx.x;
    if (idx >= GNC4) return;
    int c4 = idx & 31;
    int node = idx >> 5;             // g*NN + n
    float di = d_dinv[node];
    float s = di * di;
    float4 hv = d_h4[idx];
    float4 bv = ((const float4*)b)[c4];
    d_agg4[idx] = make_float4(hv.x*s + bv.x, hv.y*s + bv.y,
                              hv.z*s + bv.z, hv.w*s + bv.w);
}

// one warp per edge: agg[dst] += h[src] * dinv[src]*dinv[dst]   (float4 atomics)
__global__ void k_scatter(const int* __restrict__ ei) {
    int w = (blockIdx.x * blockDim.x + threadIdx.x) >> 5;
    int lane = threadIdx.x & 31;
    if (w >= G*EE) return;
    int g = w / EE, e = w % EE;
    const int* eg = ei + g*2*EE;
    int src = __ldg(&eg[e]);
    int dst = __ldg(&eg[EE + e]);
    float coef = d_dinv[g*NN + src] * d_dinv[g*NN + dst];
    float4 v = d_h4[(g*NN + src)*32 + lane];
    v.x *= coef; v.y *= coef; v.z *= coef; v.w *= coef;
    atomicAdd(&d_agg4[(g*NN + dst)*32 + lane], v);
}

__global__ void k_tanh() {
    int idx = blockIdx.x * blockDim.x + threadIdx.x;
    if (idx >= GNC4) return;
    float4 v = d_agg4[idx];
    d_act4[idx] = make_float4(tanhf(v.x), tanhf(v.y), tanhf(v.z), tanhf(v.w));
}

// pooled[g] = sum over nodes of act.  grid (G, 8), 32 threads (c4 index).
__global__ void k_pool() {
    int g = blockIdx.x, part = blockIdx.y, c4 = threadIdx.x;
    float4 s = make_float4(0.f,0.f,0.f,0.f);
    int n0 = part * 125;
    for (int n = n0; n < n0 + 125; n++) {
        float4 v = d_act4[(g*NN + n)*32 + c4];
        s.x += v.x; s.y += v.y; s.z += v.z; s.w += v.w;
    }
    atomicAdd(&d_gpool4[g*32 + c4], s);
}

// qkv = pooled @ in_w^T + in_b.  one block per graph, 384 threads.
__global__ void k_qkv(const float* __restrict__ in_w, const float* __restrict__ in_b) {
    int g = blockIdx.x, j = threadIdx.x;
    __shared__ float gr[128];
    if (j < 128) gr[j] = ((const float*)d_gpool4)[g*128 + j];
    __syncthreads();
    float s = in_b[j];
    const float* w = in_w + j*128;
    #pragma unroll 8
    for (int k = 0; k < 128; k++) s += gr[k] * w[k];
    d_qkv[g*384 + j] = s;
}

// one block per head: scores -> softmax -> attn @ V
__global__ void k_attn() {
    int h = blockIdx.x, tid = threadIdx.x;
    __shared__ float q[64][32], k[64][32], v[64][32], p[64][64];
    for (int t = tid; t < 64*32; t += 256) {
        int gg = t >> 5, dd = t & 31;
        q[gg][dd] = d_qkv[gg*384 + h*32 + dd];
        k[gg][dd] = d_qkv[gg*384 + 128 + h*32 + dd];
        v[gg][dd] = d_qkv[gg*384 + 256 + h*32 + dd];
    }
    __syncthreads();
    const float scale = 0.17677669529663687f;  // 1/sqrt(32)
    for (int t = tid; t < 64*64; t += 256) {
        int qi = t >> 6, ki = t & 63;
        float s = 0.f;
        #pragma unroll 8
        for (int dd = 0; dd < 32; dd++) s += q[qi][dd] * k[ki][dd];
        p[qi][ki] = s * scale;
    }
    __syncthreads();
    if (tid < 64) {
        float m = -1e30f;
        for (int ki = 0; ki < 64; ki++) m = fmaxf(m, p[tid][ki]);
        float sum = 0.f;
        for (int ki = 0; ki < 64; ki++) { float e = expf(p[tid][ki] - m); p[tid][ki] = e; sum += e; }
        float inv = 1.0f / sum;
        for (int ki = 0; ki < 64; ki++) p[tid][ki] *= inv;
    }
    __syncthreads();
    for (int t = tid; t < 64*32; t += 256) {
        int qi = t >> 5, dd = t & 31;
        float s = 0.f;
        #pragma unroll 8
        for (int ki = 0; ki < 64; ki++) s += p[qi][ki] * v[ki][dd];
        d_attn_o[qi*128 + h*32 + dd] = s;
    }
}

// out-proj + MLP + residual + layernorm + relu-sum into node_repr.
// one block per graph, 128 threads (thread = channel).
__global__ void k_head(const float* __restrict__ out_w, const float* __restrict__ out_b,
                       const float* __restrict__ mw1, const float* __restrict__ mb1,
                       const float* __restrict__ mw2, const float* __restrict__ mb2,
                       const float* __restrict__ lng, const float* __restrict__ lnb) {
    int g = blockIdx.x, c = threadIdx.x;
    __shared__ float o[128], xa[128], hid[256], red[128];
    o[c] = d_attn_o[g*128 + c];
    __syncthreads();
    float s = out_b[c];
    const float* w = out_w + c*128;
    #pragma unroll 8
    for (int k = 0; k < 128; k++) s += o[k] * w[k];
    xa[c] = s;
    __syncthreads();
    for (int hh = c; hh < 256; hh += 128) {
        float t = mb1[hh];
        #pragma unroll 8
        for (int k = 0; k < 128; k++) t += xa[k] * mw1[k*256 + hh];
        hid[hh] = fmaxf(t, 0.f);
    }
    __syncthreads();
    float m = mb2[c];
    #pragma unroll 8
    for (int k = 0; k < 256; k++) m += hid[k] * mw2[k*128 + c];
    float y = xa[c] + m;
    // layernorm over 128 channels
    red[c] = y; __syncthreads();
    for (int o2 = 64; o2 > 0; o2 >>= 1) { if (c < o2) red[c] += red[c + o2]; __syncthreads(); }
    float mu = red[0] * (1.f/128.f);
    __syncthreads();
    float d = y - mu;
    red[c] = d * d; __syncthreads();
    for (int o2 = 64; o2 > 0; o2 >>= 1) { if (c < o2) red[c] += red[c + o2]; __syncthreads(); }
    float var = red[0] * (1.f/128.f);
    float yn = d * rsqrtf(var + LNEPS) * lng[c] + lnb[c];
    atomicAdd(&d_node[c], fmaxf(yn, 0.f));
}

__global__ void k_final(const float* __restrict__ lw, const float* __restrict__ lb,
                        float* __restrict__ out) {
    int t = threadIdx.x;
    __shared__ float nr[128];
    nr[t] = d_node[t];
    __syncthreads();
    if (t < 2) {
        float s = lb[t];
        for (int cc = 0; cc < 128; cc++) s += nr[cc] * lw[cc*2 + t];
        out[t] = s;
    }
}

// ---------------- launch ----------------
extern "C" void kernel_launch(void* const* d_in, const int* in_sizes, int n_in,
                              void* d_out, int out_size) {
    const float* x     = (const float*)d_in[0];
    const int*   ei    = (const int*)  d_in[1];
    const float* W0    = (const float*)d_in[2];
    const float* b0    = (const float*)d_in[3];
    const float* W1    = (const float*)d_in[4];
    const float* b1    = (const float*)d_in[5];
    const float* in_w  = (const float*)d_in[6];
    const float* in_b  = (const float*)d_in[7];
    const float* out_w = (const float*)d_in[8];
    const float* out_b = (const float*)d_in[9];
    const float* lng   = (const float*)d_in[10];
    const float* lnb   = (const float*)d_in[11];
    const float* mw1   = (const float*)d_in[12];
    const float* mb1   = (const float*)d_in[13];
    const float* mw2   = (const float*)d_in[14];
    const float* mb2   = (const float*)d_in[15];
    const float* lw    = (const float*)d_in[16];
    const float* lb    = (const float*)d_in[17];
    float* out = (float*)d_out;

    k_zero<<<8, 256>>>();
    k_deg<<<G, 256>>>(ei);

    // layer 1
    k_gemm<<<1000, 256>>>(x, 0, W0);
    k_initagg<<<GNC4/256, 256>>>(b0);
    k_scatter<<<(G*EE)/8, 256>>>(ei);     // 8 warps (edges) per 256-thread block
    k_tanh<<<GNC4/256, 256>>>();

    // layer 2
    k_gemm<<<1000, 256>>>(nullptr, 1, W1);
    k_initagg<<<GNC4/256, 256>>>(b1);
    k_scatter<<<(G*EE)/8, 256>>>(ei);
    k_tanh<<<GNC4/256, 256>>>();

    // head
    k_pool<<<dim3(G, 8), 32>>>();
    k_qkv<<<G, 384>>>(in_w, in_b);
    k_attn<<<NH, 256>>>();
    k_head<<<G, 128>>>(out_w, out_b, mw1, mb1, mw2, mb2, lng, lnb);
    k_final<<<1, 128>>>(lw, lb, out);
}

// round 2
// speedup vs baseline: 1.2341x; 1.2341x over previous
#include <cuda_runtime.h>
#include <cuda_bf16.h>

#define G   64
#define NN  1000
#define EE  8192
#define C   128
#define HID 256
#define NH  4
#define LNEPS 1e-5f

#define GNC4 (G*NN*32)   // float4 elements in a (G,N,C) buffer

// ---------------- scratch (device globals: no allocations allowed) ----------------
__device__ float4 d_h4[GNC4];        // GEMM output h = X @ W
__device__ float4 d_act4[GNC4];      // tanh(aggregated) activation
__device__ float  d_dinv[G*NN];      // 1/sqrt(deg)
__device__ int    d_off[G*(NN+1)];   // CSR row offsets (by dst)
__device__ int2   d_csr[G*EE];       // per-edge {src, coef-bits}
__device__ float4 d_gpool4[G*32];    // pooled graph features (G,128)
__device__ float  d_qkv[G*3*C];
__device__ float  d_attn_o[G*C];
__device__ float  d_node[C];         // node_repr accumulator

// ---------------- kernels ----------------

__global__ void k_zero() {
    int i = blockIdx.x * blockDim.x + threadIdx.x;
    if (i < G*32) d_gpool4[i] = make_float4(0.f,0.f,0.f,0.f);
    if (i < C)    d_node[i] = 0.f;
}

// Per-graph: degree -> dinv, CSR by dst (counting sort), edge coef precompute.
__global__ void k_build(const int* __restrict__ ei) {
    int g = blockIdx.x;
    __shared__ int   cnt[NN+1];
    __shared__ float dinv_s[NN];
    for (int i = threadIdx.x; i <= NN; i += blockDim.x) cnt[i] = 0;
    __syncthreads();
    const int* srcp = ei + g*2*EE;
    const int* dstp = srcp + EE;
    for (int e = threadIdx.x; e < EE; e += blockDim.x)
        atomicAdd(&cnt[dstp[e] + 1], 1);
    __syncthreads();
    for (int i = threadIdx.x; i < NN; i += blockDim.x) {
        float di = rsqrtf((float)cnt[i+1] + 1.0f);
        dinv_s[i] = di;
        d_dinv[g*NN + i] = di;
    }
    __syncthreads();
    if (threadIdx.x == 0)
        for (int i = 1; i <= NN; i++) cnt[i] += cnt[i-1];   // inclusive scan -> row starts
    __syncthreads();
    for (int i = threadIdx.x; i <= NN; i += blockDim.x)
        d_off[g*(NN+1) + i] = cnt[i];
    __syncthreads();
    for (int e = threadIdx.x; e < EE; e += blockDim.x) {
        int s = srcp[e], d = dstp[e];
        int pos = atomicAdd(&cnt[d], 1);
        float coef = dinv_s[s] * dinv_s[d];
        d_csr[g*EE + pos] = make_int2(s, __float_as_int(coef));
    }
}

// Y(=d_h4) = X @ W,  X: 64000x128, W: 128x128.  BM=64, full N=128 per block.
// Inner loop uses packed fma.rn.f32x2 (2x fp32 FMA throughput on sm_100a,
// identical IEEE rounding to scalar FFMA).
__global__ void k_gemm(const float* __restrict__ Xext, int useAct,
                       const float* __restrict__ W) {
    const float* X = useAct ? (const float*)d_act4 : Xext;
    float* Y = (float*)d_h4;
    __shared__ __align__(16) float Xs[64][32];
    __shared__ __align__(16) float Ws[32][128];
    int tid = threadIdx.x;              // 256 threads
    int row0 = blockIdx.x * 64;
    int cg = tid & 31;                  // cols cg*4..cg*4+3
    int rg = tid >> 5;                  // rows rg*8..rg*8+7
    unsigned long long acc[8][2];
    #pragma unroll
    for (int i = 0; i < 8; i++) { acc[i][0] = 0ull; acc[i][1] = 0ull; }

    for (int k0 = 0; k0 < 128; k0 += 32) {
        for (int t = tid; t < 512; t += 256) {          // Xs: 64x32
            int r = t >> 3, c4 = t & 7;
            *(float4*)&Xs[r][c4*4] = *(const float4*)&X[(row0 + r)*128 + k0 + c4*4];
        }
        for (int t = tid; t < 1024; t += 256) {         // Ws: 32x128
            int r = t >> 5, c4 = t & 31;
            *(float4*)&Ws[r][c4*4] = *(const float4*)&W[(k0 + r)*128 + c4*4];
        }
        __syncthreads();
        #pragma unroll
        for (int kk = 0; kk < 32; kk++) {
            ulonglong2 w = *(ulonglong2*)&Ws[kk][cg*4];
            #pragma unroll
            for (int i = 0; i < 8; i++) {
                float a = Xs[rg*8 + i][kk];
                unsigned long long ap;
                asm("mov.b64 %0,{%1,%1};" : "=l"(ap) : "f"(a));
                asm("fma.rn.f32x2 %0,%1,%2,%0;" : "+l"(acc[i][0]) : "l"(ap), "l"(w.x));
                asm("fma.rn.f32x2 %0,%1,%2,%0;" : "+l"(acc[i][1]) : "l"(ap), "l"(w.y));
            }
        }
        __syncthreads();
    }
    #pragma unroll
    for (int i = 0; i < 8; i++) {
        float2 lo = *(float2*)&acc[i][0];
        float2 hi = *(float2*)&acc[i][1];
        *(float4*)&Y[(row0 + rg*8 + i)*128 + cg*4] = make_float4(lo.x, lo.y, hi.x, hi.y);
    }
}

// Warp-per-node CSR gather + self-loop + bias + tanh, fused epilogues:
//   layer1: write act
//   layer2: atomic-accumulate into graph pool (act2 never materialized)
__global__ void k_gather(const float4* __restrict__ b4, int layer2) {
    int w = (blockIdx.x * blockDim.x + threadIdx.x) >> 5;
    int lane = threadIdx.x & 31;
    if (w >= G*NN) return;
    int g = w / NN, n = w % NN;
    float din = d_dinv[w];
    float s = din * din;
    float4 acc = d_h4[w*32 + lane];
    float4 bv = b4[lane];
    acc.x = acc.x*s + bv.x; acc.y = acc.y*s + bv.y;
    acc.z = acc.z*s + bv.z; acc.w = acc.w*s + bv.w;
    int start = d_off[g*(NN+1) + n];
    int end   = d_off[g*(NN+1) + n + 1];
    const int2* cs = d_csr + g*EE;
    const float4* hbase = d_h4 + (size_t)g*NN*32;
    for (int i = start; i < end; i++) {
        int2 e = __ldg(&cs[i]);
        float coef = __int_as_float(e.y);
        float4 v = hbase[e.x*32 + lane];
        acc.x += v.x*coef; acc.y += v.y*coef;
        acc.z += v.z*coef; acc.w += v.w*coef;
    }
    acc.x = tanhf(acc.x); acc.y = tanhf(acc.y);
    acc.z = tanhf(acc.z); acc.w = tanhf(acc.w);
    if (!layer2) d_act4[w*32 + lane] = acc;
    else         atomicAdd(&d_gpool4[g*32 + lane], acc);
}

// qkv = pooled @ in_w^T + in_b.  one block per graph, 384 threads.
__global__ void k_qkv(const float* __restrict__ in_w, const float* __restrict__ in_b) {
    int g = blockIdx.x, j = threadIdx.x;
    __shared__ float gr[128];
    if (j < 128) gr[j] = ((const float*)d_gpool4)[g*128 + j];
    __syncthreads();
    float s = in_b[j];
    const float* w = in_w + j*128;
    #pragma unroll 8
    for (int k = 0; k < 128; k++) s += gr[k] * w[k];
    d_qkv[g*384 + j] = s;
}

// one block per head: scores -> softmax -> attn @ V
__global__ void k_attn() {
    int h = blockIdx.x, tid = threadIdx.x;
    __shared__ float q[64][32], k[64][32], v[64][32], p[64][64];
    for (int t = tid; t < 64*32; t += 256) {
        int gg = t >> 5, dd = t & 31;
        q[gg][dd] = d_qkv[gg*384 + h*32 + dd];
        k[gg][dd] = d_qkv[gg*384 + 128 + h*32 + dd];
        v[gg][dd] = d_qkv[gg*384 + 256 + h*32 + dd];
    }
    __syncthreads();
    const float scale = 0.17677669529663687f;  // 1/sqrt(32)
    for (int t = tid; t < 64*64; t += 256) {
        int qi = t >> 6, ki = t & 63;
        float s = 0.f;
        #pragma unroll 8
        for (int dd = 0; dd < 32; dd++) s += q[qi][dd] * k[ki][dd];
        p[qi][ki] = s * scale;
    }
    __syncthreads();
    if (tid < 64) {
        float m = -1e30f;
        for (int ki = 0; ki < 64; ki++) m = fmaxf(m, p[tid][ki]);
        float sum = 0.f;
        for (int ki = 0; ki < 64; ki++) { float e = expf(p[tid][ki] - m); p[tid][ki] = e; sum += e; }
        float inv = 1.0f / sum;
        for (int ki = 0; ki < 64; ki++) p[tid][ki] *= inv;
    }
    __syncthreads();
    for (int t = tid; t < 64*32; t += 256) {
        int qi = t >> 5, dd = t & 31;
        float s = 0.f;
        #pragma unroll 8
        for (int ki = 0; ki < 64; ki++) s += p[qi][ki] * v[ki][dd];
        d_attn_o[qi*128 + h*32 + dd] = s;
    }
}

// out-proj + MLP + residual + layernorm + relu-sum into node_repr.
__global__ void k_head(const float* __restrict__ out_w, const float* __restrict__ out_b,
                       const float* __restrict__ mw1, const float* __restrict__ mb1,
                       const float* __restrict__ mw2, const float* __restrict__ mb2,
                       const float* __restrict__ lng, const float* __restrict__ lnb) {
    int g = blockIdx.x, c = threadIdx.x;
    __shared__ float o[128], xa[128], hid[256], red[128];
    o[c] = d_attn_o[g*128 + c];
    __syncthreads();
    float s = out_b[c];
    const float* w = out_w + c*128;
    #pragma unroll 8
    for (int k = 0; k < 128; k++) s += o[k] * w[k];
    xa[c] = s;
    __syncthreads();
    for (int hh = c; hh < 256; hh += 128) {
        float t = mb1[hh];
        #pragma unroll 8
        for (int k = 0; k < 128; k++) t += xa[k] * mw1[k*256 + hh];
        hid[hh] = fmaxf(t, 0.f);
    }
    __syncthreads();
    float m = mb2[c];
    #pragma unroll 8
    for (int k = 0; k < 256; k++) m += hid[k] * mw2[k*128 + c];
    float y = xa[c] + m;
    red[c] = y; __syncthreads();
    for (int o2 = 64; o2 > 0; o2 >>= 1) { if (c < o2) red[c] += red[c + o2]; __syncthreads(); }
    float mu = red[0] * (1.f/128.f);
    __syncthreads();
    float d = y - mu;
    red[c] = d * d; __syncthreads();
    for (int o2 = 64; o2 > 0; o2 >>= 1) { if (c < o2) red[c] += red[c + o2]; __syncthreads(); }
    float var = red[0] * (1.f/128.f);
    float yn = d * rsqrtf(var + LNEPS) * lng[c] + lnb[c];
    atomicAdd(&d_node[c], fmaxf(yn, 0.f));
}

__global__ void k_final(const float* __restrict__ lw, const float* __restrict__ lb,
                        float* __restrict__ out) {
    int t = threadIdx.x;
    __shared__ float nr[128];
    nr[t] = d_node[t];
    __syncthreads();
    if (t < 2) {
        float s = lb[t];
        for (int cc = 0; cc < 128; cc++) s += nr[cc] * lw[cc*2 + t];
        out[t] = s;
    }
}

// ---------------- launch ----------------
extern "C" void kernel_launch(void* const* d_in, const int* in_sizes, int n_in,
                              void* d_out, int out_size) {
    const float* x     = (const float*)d_in[0];
    const int*   ei    = (const int*)  d_in[1];
    const float* W0    = (const float*)d_in[2];
    const float* b0    = (const float*)d_in[3];
    const float* W1    = (const float*)d_in[4];
    const float* b1    = (const float*)d_in[5];
    const float* in_w  = (const float*)d_in[6];
    const float* in_b  = (const float*)d_in[7];
    const float* out_w = (const float*)d_in[8];
    const float* out_b = (const float*)d_in[9];
    const float* lng   = (const float*)d_in[10];
    const float* lnb   = (const float*)d_in[11];
    const float* mw1   = (const float*)d_in[12];
    const float* mb1   = (const float*)d_in[13];
    const float* mw2   = (const float*)d_in[14];
    const float* mb2   = (const float*)d_in[15];
    const float* lw    = (const float*)d_in[16];
    const float* lb    = (const float*)d_in[17];
    float* out = (float*)d_out;

    k_zero<<<8, 256>>>();
    k_build<<<G, 256>>>(ei);

    // layer 1
    k_gemm<<<1000, 256>>>(x, 0, W0);
    k_gather<<<8000, 256>>>((const float4*)b0, 0);

    // layer 2
    k_gemm<<<1000, 256>>>(nullptr, 1, W1);
    k_gather<<<8000, 256>>>((const float4*)b1, 1);

    // head
    k_qkv<<<G, 384>>>(in_w, in_b);
    k_attn<<<NH, 256>>>();
    k_head<<<G, 128>>>(out_w, out_b, mw1, mb1, mw2, mb2, lng, lnb);
    k_final<<<1, 128>>>(lw, lb, out);
}